// round 17
// baseline (speedup 1.0000x reference)
#include <cuda_runtime.h>
#include <cuda_fp16.h>
#include <stdint.h>
#include <stddef.h>

// ---------------------------------------------------------------------------
// out = softmax(Q K^T / sqrt(D) + tril(ones)) V ;  B=16, S=2048, D=3072, fp32
// sm_103 base-target only: cp.async + ldmatrix + mma.sync (no tcgen05/TMA).
// R15 config (best) + conflict-free two-phase V transpose in the convert.
// ---------------------------------------------------------------------------
#define BB 16
#define SS 2048
#define DD 3072
#define SCALE 0.01804219591217581f  // 1/sqrt(3072)

__device__ __align__(128) __half g_Qh[(size_t)BB * SS * DD];   // (b, sT16, kT48)
__device__ __align__(128) __half g_Kh[(size_t)BB * SS * DD];   // (b, tT16, kT48)
__device__ __align__(128) __half g_Vt[(size_t)BB * SS * DD];   // (b, dT24, kT32) row=d,col=t
__device__ __align__(128) __half g_P [(size_t)BB * SS * SS];   // (b, sT16, tT32)
__device__ __align__(128) float  g_rs[(size_t)BB * SS * 32];   // 32 partial rowsums per row

#define SWZ(o) ((o) ^ (((o) >> 3) & 0x70))

static __device__ __forceinline__ uint32_t smem_u32(const void* p) {
    uint32_t a;
    asm("{ .reg .u64 t; cvta.to.shared.u64 t, %1; cvt.u32.u64 %0, t; }" : "=r"(a) : "l"(p));
    return a;
}
static __device__ __forceinline__ void cp16(uint32_t dst, const void* src) {
    unsigned long long g = __cvta_generic_to_global(src);
    asm volatile("cp.async.cg.shared.global [%0], [%1], 16;" :: "r"(dst), "l"(g) : "memory");
}
static __device__ __forceinline__ void mbar_init(uint32_t a, uint32_t c) {
    asm volatile("mbarrier.init.shared.b64 [%0], %1;" :: "r"(a), "r"(c) : "memory");
}
static __device__ __forceinline__ void mbar_arrive(uint32_t a) {
    asm volatile("mbarrier.arrive.shared.b64 _, [%0];" :: "r"(a) : "memory");
}
// arrive on mbar once all of THIS thread's prior cp.asyncs have completed
static __device__ __forceinline__ void cpasync_mbar_arrive(uint32_t a) {
    asm volatile("cp.async.mbarrier.arrive.noinc.shared::cta.b64 [%0];" :: "r"(a) : "memory");
}
static __device__ __forceinline__ void mbar_wait(uint32_t mbar, uint32_t parity) {
    uint32_t done = 0;
    while (!done) {
        asm volatile(
            "{\n\t.reg .pred p;\n\t"
            "mbarrier.try_wait.parity.acquire.cta.shared::cta.b64 p, [%1], %2, 0x989680;\n\t"
            "selp.b32 %0, 1, 0, p;\n\t}"
            : "=r"(done) : "r"(mbar), "r"(parity) : "memory");
    }
}

static __device__ __forceinline__ void ldsm4(uint32_t* r, uint32_t addr) {
    asm volatile("ldmatrix.sync.aligned.m8n8.x4.shared.b16 {%0,%1,%2,%3}, [%4];"
                 : "=r"(r[0]), "=r"(r[1]), "=r"(r[2]), "=r"(r[3]) : "r"(addr));
}
static __device__ __forceinline__ void hmma(float* d, const uint32_t* a, const uint32_t* b) {
    asm volatile(
        "mma.sync.aligned.m16n8k16.row.col.f32.f16.f16.f32 "
        "{%0,%1,%2,%3}, {%4,%5,%6,%7}, {%8,%9}, {%0,%1,%2,%3};"
        : "+f"(d[0]), "+f"(d[1]), "+f"(d[2]), "+f"(d[3])
        : "r"(a[0]), "r"(a[1]), "r"(a[2]), "r"(a[3]), "r"(b[0]), "r"(b[1]));
}

// ---------------------------------------------------------------------------
// Fused fp32 -> fp16 block-swizzled convert for Q, K and V.
// grid (48, 56, 16): y<16 Q(sT=y), y<32 K(sT=y-16), y>=32 V(dT=y-32, x<32).
// V path: two-phase transpose. Phase 1 coalesced float4 loads -> linear smem
// [64][132] (conflict-free). Phase 2 column gather (bank = (4*tt+dd)%32,
// 2-way max) -> half2 pack -> swizzled 16B stores; thread pairs cover full
// 128B rows so warp stores stay line-coalesced despite the swizzle.
// ---------------------------------------------------------------------------
__global__ __launch_bounds__(256) void k_conv_all(
    const float* __restrict__ q, const float* __restrict__ k,
    const float* __restrict__ v)
{
    __shared__ __align__(16) float tf[64 * 132];
    const int job = blockIdx.y, b = blockIdx.z, tid = threadIdx.x;
    if (job < 32) {
        const float* src = (job < 16) ? q : k;
        __half* dst = (job < 16) ? g_Qh : g_Kh;
        const int sT = job & 15, kT = blockIdx.x;
        const float* s0 = src + ((size_t)(b * SS) + sT * 128) * DD + kT * 64;
        __half* d0 = dst + ((size_t)((b * 16 + sT) * 48 + kT)) * 8192;
#pragma unroll
        for (int j = 0; j < 4; j++) {
            int e = (j * 256 + tid) * 8;
            int r = e >> 6, c = e & 63;
            const float4* p = (const float4*)(s0 + (size_t)r * DD + c);
            float4 f0 = p[0], f1 = p[1];
            __half2 h0 = __floats2half2_rn(f0.x, f0.y), h1 = __floats2half2_rn(f0.z, f0.w);
            __half2 h2 = __floats2half2_rn(f1.x, f1.y), h3 = __floats2half2_rn(f1.z, f1.w);
            uint4 u;
            u.x = *(const uint32_t*)&h0; u.y = *(const uint32_t*)&h1;
            u.z = *(const uint32_t*)&h2; u.w = *(const uint32_t*)&h3;
            *(uint4*)((char*)d0 + SWZ((uint32_t)(r * 128 + c * 2))) = u;
        }
    } else {
        if (blockIdx.x >= 32) return;
        const int dT = job - 32, kT = blockIdx.x;
        const float* s0 = v + ((size_t)(b * SS) + kT * 64) * DD + dT * 128;
        // Phase 1: coalesced loads (warp covers one full 512B t-row)
#pragma unroll
        for (int j = 0; j < 8; j++) {
            int e = j * 256 + tid;
            int tt = e >> 5, dd4 = (e & 31) * 4;
            float4 f = *(const float4*)(s0 + (size_t)tt * DD + dd4);
            *(float4*)(tf + tt * 132 + dd4) = f;
        }
        __syncthreads();
        // Phase 2: transpose + convert + swizzled coalesced stores
        __half* d0 = g_Vt + ((size_t)((b * 24 + dT) * 32 + kT)) * 8192;
        const int dd = tid >> 1, tt0 = (tid & 1) * 32;
#pragma unroll
        for (int u = 0; u < 4; u++) {
            int tb0 = tt0 + u * 8;
            uint32_t h[4];
#pragma unroll
            for (int i = 0; i < 4; i++) {
                float f0 = tf[(tb0 + 2 * i) * 132 + dd];
                float f1 = tf[(tb0 + 2 * i + 1) * 132 + dd];
                __half2 hh = __floats2half2_rn(f0, f1);
                h[i] = *(const uint32_t*)&hh;
            }
            uint4 u4 = make_uint4(h[0], h[1], h[2], h[3]);
            *(uint4*)((char*)d0 + SWZ((uint32_t)(dd * 128 + tb0 * 2))) = u4;
        }
    }
}

// ---------------------------------------------------------------------------
// GEMM: CTA 128x128, K-chunk 64, 3-stage mbarrier cp.async pipeline,
// 256 threads / 8 warps (4m x 2n), warp tile 32x64, 2 CTAs per SM.
// MODE 0: exp epilogue -> P (fp16 swizzled) + partial rowsums
// MODE 1: normalize epilogue -> fp32 out (rowsum load deferred past issue)
// ---------------------------------------------------------------------------
#define STAGE_BYTES 32768
#define MBAR_OFF    (3 * STAGE_BYTES)
#define SMEM_BYTES  (3 * STAGE_BYTES + 1024)

template<int NK, int NBT, int MODE>
__global__ __launch_bounds__(256, 2) void k_gemm(
    const __half* __restrict__ Ab, const __half* __restrict__ Bb,
    float* __restrict__ out)
{
    extern __shared__ __align__(1024) char sm[];
    const int tid = threadIdx.x, wid = tid >> 5, lane = tid & 31;
    const int nT = blockIdx.x, sT = blockIdx.y, b = blockIdx.z;
    const uint32_t smb = smem_u32(sm);
    const uint32_t MB = smb + MBAR_OFF;          // full(s)=MB+16s, empty=+8
    float* sinv = (float*)(sm + MBAR_OFF + 64);

    const __half* aBase = Ab + ((size_t)(b * 16 + sT) * NK) * 8192;
    const __half* bBase = Bb + ((size_t)(b * NBT + nT) * NK) * 8192;

    if (tid == 0) {
#pragma unroll
        for (int s = 0; s < 3; s++) {
            mbar_init(MB + 16 * s, 256);         // full
            mbar_init(MB + 16 * s + 8, 256);     // empty
        }
    }
    __syncthreads();

    // copy chunk k (A 16KB + B 16KB) into stage k%3 (no commit groups)
    auto issue = [&](int k) {
        uint32_t st = smb + (uint32_t)(k % 3) * STAGE_BYTES;
#pragma unroll
        for (int j = 0; j < 8; j++) {
            int idx = j * 256 + tid;
            int blk = idx >> 10, ru = idx & 1023;
            const char* src = (const char*)((blk ? bBase : aBase) +
                              (size_t)k * 8192) + ru * 16;
            cp16(st + (uint32_t)blk * 16384u + (uint32_t)ru * 16u, src);
        }
    };
    issue(0); cpasync_mbar_arrive(MB + 0);
    issue(1); cpasync_mbar_arrive(MB + 16);

    if (MODE == 1 && tid < 128) {                // after pipeline start
        const float* rr = g_rs + ((size_t)(b * SS) + sT * 128 + tid) * 32;
        float s = 0.f;
#pragma unroll
        for (int i = 0; i < 8; i++) {
            float4 v = *(const float4*)(rr + i * 4);
            s += v.x + v.y + v.z + v.w;
        }
        sinv[tid] = 1.f / s;
    }

    float acc[2][8][4];
#pragma unroll
    for (int i = 0; i < 2; i++)
#pragma unroll
        for (int j = 0; j < 8; j++)
#pragma unroll
            for (int q = 0; q < 4; q++) acc[i][j][q] = 0.f;

    const int wm = wid & 3, wn = wid >> 2;       // 4 m-groups x 2 n-groups
    const int g2 = lane >> 3, ri = lane & 7;
    const int arow = wm * 32 + (g2 & 1) * 8 + ri;
    const int brow = wn * 64 + (g2 & 1) * 8 + ri;

    // SWZ(row*128+col) = row*128 + (col ^ ((row&7)*16)); fold invariants.
    const uint32_t colhi = (uint32_t)(g2 >> 1) * 16;
    const uint32_t cba = colhi ^ ((uint32_t)(arow & 7) * 16);
    const uint32_t cbb = colhi ^ ((uint32_t)(brow & 7) * 16);
    const uint32_t aoffc = (uint32_t)arow * 128;
    const uint32_t boffc = 16384u + (uint32_t)brow * 128;

    for (int k = 0; k < NK; k++) {
        const int s = k % 3;
        const int kd3 = k / 3;
        mbar_wait(MB + 16 * s, (uint32_t)(kd3 & 1));   // stage s full, acquire
        uint32_t sa = smb + (uint32_t)s * STAGE_BYTES;
#pragma unroll
        for (int kss = 0; kss < 4; kss++) {
            const uint32_t ca = cba ^ (uint32_t)(kss * 32);
            const uint32_t cb = cbb ^ (uint32_t)(kss * 32);
            uint32_t af[2][4], bf[8][2];
#pragma unroll
            for (int mf = 0; mf < 2; mf++)
                ldsm4(af[mf], sa + aoffc + (uint32_t)(mf * 2048) + ca);
#pragma unroll
            for (int f = 0; f < 4; f++) {
                uint32_t tb4[4];
                ldsm4(tb4, sa + boffc + (uint32_t)(f * 2048) + cb);
                bf[2 * f][0] = tb4[0]; bf[2 * f + 1][0] = tb4[1];
                bf[2 * f][1] = tb4[2]; bf[2 * f + 1][1] = tb4[3];
            }
#pragma unroll
            for (int mf = 0; mf < 2; mf++)
#pragma unroll
                for (int nf = 0; nf < 8; nf++)
                    hmma(acc[mf][nf], af[mf], bf[nf]);
        }
        mbar_arrive(MB + 16 * s + 8);             // done reading stage s (early)
        const int kp = k + 2;
        if (kp < NK) {
            const int sp = kp % 3;
            if (kp >= 3)                          // stage reuse: wait empties
                mbar_wait(MB + 16 * sp + 8, (uint32_t)(((kp / 3) - 1) & 1));
            issue(kp);
            cpasync_mbar_arrive(MB + 16 * sp);
        }
    }
    __syncthreads();                              // all warps done; smem reusable

    const int g = lane >> 2, t4 = lane & 3;

    if (MODE == 0) {
#pragma unroll
        for (int mf = 0; mf < 2; mf++) {
#pragma unroll
            for (int hi = 0; hi < 2; hi++) {
                int row = wm * 32 + mf * 16 + hi * 8 + g;
                int sglob = sT * 128 + row;
                float rsum = 0.f;
#pragma unroll
                for (int nf = 0; nf < 8; nf++) {
                    int c = wn * 64 + nf * 8 + 2 * t4;
                    int tg = nT * 128 + c;
                    float x0 = acc[mf][nf][hi * 2]     * SCALE + ((tg     <= sglob) ? 1.f : 0.f);
                    float x1 = acc[mf][nf][hi * 2 + 1] * SCALE + ((tg + 1 <= sglob) ? 1.f : 0.f);
                    float p0 = __expf(x0), p1 = __expf(x1);
                    rsum += p0 + p1;
                    __half2 h = __floats2half2_rn(p0, p1);
                    uint32_t off = (uint32_t)(c >> 6) * 16384 +
                                   SWZ((uint32_t)(row * 128 + (c & 63) * 2));
                    *(__half2*)(sm + off) = h;
                }
                rsum += __shfl_xor_sync(~0u, rsum, 1);
                rsum += __shfl_xor_sync(~0u, rsum, 2);
                if (t4 == 0)
                    g_rs[((size_t)(b * SS) + sglob) * 32 + nT * 2 + wn] = rsum;
            }
        }
        __syncthreads();
        __half* pdst = g_P + ((size_t)((b * 16 + sT) * 32 + nT * 2)) * 8192;
        const uint4* s4 = (const uint4*)sm;
        uint4* g4 = (uint4*)pdst;
        for (int i = tid; i < 2048; i += 256) g4[i] = s4[i];
    } else {
#pragma unroll
        for (int mf = 0; mf < 2; mf++) {
#pragma unroll
            for (int hi = 0; hi < 2; hi++) {
                int row = wm * 32 + mf * 16 + hi * 8 + g;
                float inv = sinv[row];
#pragma unroll
                for (int nf = 0; nf < 8; nf++) {
                    int c = wn * 64 + nf * 8 + 2 * t4;
                    float2 v;
                    v.x = acc[mf][nf][hi * 2]     * inv;
                    v.y = acc[mf][nf][hi * 2 + 1] * inv;
                    *(float2*)(sm + (size_t)(row * 132 + c) * 4) = v;
                }
            }
        }
        __syncthreads();
        float* obase = out + ((size_t)(b * SS) + sT * 128) * DD + nT * 128;
        for (int i = tid; i < 4096; i += 256) {
            int row = i >> 5, c = (i & 31) * 4;
            float4 v = *(const float4*)(sm + (size_t)(row * 132 + c) * 4);
            *(float4*)(obase + (size_t)row * DD + c) = v;
        }
    }
}

// ---------------------------------------------------------------------------
extern "C" void kernel_launch(void* const* d_in, const int* in_sizes, int n_in,
                              void* d_out, int out_size) {
    (void)in_sizes; (void)n_in; (void)out_size;
    const float* q = (const float*)d_in[1];
    const float* k = (const float*)d_in[2];
    const float* v = (const float*)d_in[3];
    float* out = (float*)d_out;

    static int init = 0;
    if (!init) {
        cudaFuncSetAttribute(k_gemm<48, 16, 0>, cudaFuncAttributeMaxDynamicSharedMemorySize, SMEM_BYTES);
        cudaFuncSetAttribute(k_gemm<32, 24, 1>, cudaFuncAttributeMaxDynamicSharedMemorySize, SMEM_BYTES);
        init = 1;
    }

    void *pQ = nullptr, *pK = nullptr, *pVt = nullptr, *pP = nullptr;
    cudaGetSymbolAddress(&pQ, g_Qh);
    cudaGetSymbolAddress(&pK, g_Kh);
    cudaGetSymbolAddress(&pVt, g_Vt);
    cudaGetSymbolAddress(&pP, g_P);

    // All three converts in one launch (one wave-tail instead of three).
    k_conv_all<<<dim3(48, 56, 16), 256>>>(q, k, v);
    // GEMM1: logits -> exp -> P + rowsums. grid (nT=16, sT=16, b=16)
    k_gemm<48, 16, 0><<<dim3(16, 16, 16), 256, SMEM_BYTES>>>(
        (const __half*)pQ, (const __half*)pK, nullptr);
    // GEMM2: P @ Vt -> normalized out. grid (nT=24, sT=16, b=16)
    k_gemm<32, 24, 1><<<dim3(24, 16, 16), 256, SMEM_BYTES>>>(
        (const __half*)pP, (const __half*)pVt, out);
}